// round 11
// baseline (speedup 1.0000x reference)
#include <cuda_runtime.h>
#include <cuda_bf16.h>
#include <cstdint>

#define B_ 2
#define H_ 12
#define S_ 256
#define E_ 64
#define D_ 768
#define L_ 25
#define RS (S_ * D_)      // rel sq-stride (floats)
#define CH 24             // k32 chunks
#define RSTR 40           // raw row stride (floats) = 160B
#define RBUFF (16 * RSTR) // floats per raw buffer (640)
#define NBUF 3
#define TPB 512
#define GSTRIDE 3076      // u32 per g-block of W frags (12304B, /16 odd -> conflict-free)
#define WQ_U32 (8 * GSTRIDE)  // 24608

typedef unsigned long long u64;
typedef unsigned int u32;

// ---- smem layout (float-slot offsets) ----
#define OFF_WS   0                      // 24608 u32
#define OFF_RAW  24608                  // 16 warps x 3 bufs x 640 = 30720
#define OFF_VS   55328                  // 768
#define OFF_CVS  56096                  // 300
#define OFF_BIAS 56396                  // 32
#define SMEM_FLOATS 56428               // 225712 bytes

__device__ float g_pt[B_ * H_ * S_ * S_];
__device__ u32   g_wp[WQ_U32];

__device__ __forceinline__ u32 f2tf32(float x) {
    u32 r;
    asm("cvt.rna.tf32.f32 %0, %1;" : "=r"(r) : "f"(x));
    return r;
}

// z<24: transpose p; z==24: pack W into g-major tf32 frag layout.
// Logical k-map for (chunk c, kstep s=2h+e, tg): k0 = 32c+16h+4tg+2e, k1 = k0+1.
// wq[g][ks][tg] holds 4 nt pairs (b0,b1): u32 index g*GSTRIDE + (ks*4+tg)*8 + nt*2 + j.
__global__ void prep_kernel(const float* __restrict__ p, const float* __restrict__ W) {
    if (blockIdx.z == 24) {
        int flat = blockIdx.y * 8 + blockIdx.x;      // 0..63
        int t = flat * 256 + threadIdx.y * 32 + threadIdx.x;
        if (t >= 96 * 32 * 4) return;                 // 96 ksteps x 32 n x 4 tg
        int ks = t >> 7;
        int r  = t & 127;
        int n  = r >> 2, tg = r & 3;
        int c = ks >> 2, s = ks & 3;
        int h = s >> 1, e = s & 1;
        int k0 = c * 32 + h * 16 + tg * 4 + e * 2;
#pragma unroll
        for (int j = 0; j < 2; ++j) {
            float wv = (n < L_) ? W[n * D_ + k0 + j] : 0.0f;
            g_wp[(n & 7) * GSTRIDE + (ks * 4 + tg) * 8 + (n >> 3) * 2 + j] = f2tf32(wv);
        }
        return;
    }
    __shared__ float tile[32][33];
    int bh = blockIdx.z, x0 = blockIdx.x * 32, y0 = blockIdx.y * 32;
    int tx = threadIdx.x, ty = threadIdx.y;
    const float* src = p + (size_t)bh * (S_ * S_);
#pragma unroll
    for (int j = 0; j < 32; j += 8)
        tile[ty + j][tx] = src[(size_t)(y0 + ty + j) * S_ + (x0 + tx)];
    __syncthreads();
    float* dst = g_pt + (size_t)bh * (S_ * S_);
#pragma unroll
    for (int j = 0; j < 32; j += 8)
        dst[(size_t)(x0 + ty + j) * S_ + (y0 + tx)] = tile[tx][ty + j];
}

__device__ __forceinline__ void cpasync16(u32 dst, const float* src) {
    asm volatile("cp.async.cg.shared.global [%0], [%1], 16;\n" :: "r"(dst), "l"(src));
}
__device__ __forceinline__ void cp_commit() {
    asm volatile("cp.async.commit_group;\n" ::: "memory");
}
__device__ __forceinline__ void cp_wait2() {
    asm volatile("cp.async.wait_group 2;\n" ::: "memory");
}
__device__ __forceinline__ u32 smem_u32(const void* p) {
    u32 r;
    asm("{ .reg .u64 t; cvta.to.shared.u64 t, %1; cvt.u32.u64 %0, t; }" : "=r"(r) : "l"(p));
    return r;
}
__device__ __forceinline__ void mma_tf32(float* c, const u32* a, u32 b0, u32 b1) {
    asm volatile(
        "mma.sync.aligned.m16n8k8.row.col.f32.tf32.tf32.f32 "
        "{%0,%1,%2,%3}, {%4,%5,%6,%7}, {%8,%9}, {%0,%1,%2,%3};"
        : "+f"(c[0]), "+f"(c[1]), "+f"(c[2]), "+f"(c[3])
        : "r"(a[0]), "r"(a[1]), "r"(a[2]), "r"(a[3]), "r"(b0), "r"(b1));
}

__global__ void __launch_bounds__(TPB, 1) mhs_mma_kernel(
    const float* __restrict__ v,     // [B,H,S,E]
    const float* __restrict__ rel,   // [B,S,S,768]
    const float* __restrict__ W,     // [25,768] fp32
    const float* __restrict__ bias,  // [25]
    float* __restrict__ out)         // [B,S,25,S]
{
    extern __shared__ float smem[];
    const int tid  = threadIdx.x;
    const int w    = tid >> 5;           // warp 0..15, owns sq rows 16w..16w+15
    const int lane = tid & 31;
    const int g    = lane >> 2;          // groupID
    const int tg   = lane & 3;           // thread-in-group

    const int blk = blockIdx.x;
    const int b   = blk >> 8;
    const int sk  = blk & 255;

    float* v_s    = smem + OFF_VS;
    float* cv_s   = smem + OFF_CVS;
    float* bias_s = smem + OFF_BIAS;
    float* rawb   = smem + OFF_RAW + w * (NBUF * RBUFF);
    const u32 raw_su = smem_u32(rawb);
    const u32* wsg = (const u32*)smem + g * GSTRIDE;   // this lane's W g-block

    const float* relb  = rel + (size_t)b * S_ * RS + (size_t)sk * D_;
    const float* myrel = relb + (size_t)(16 * w) * RS;

    // cp.async lane mapping: 4 instrs/chunk, instr i covers rows 4i..4i+3,
    // lane: row_local = lane>>3, seg = lane&7 (16B each, 128B contiguous/row)
    const int crow = lane >> 3;          // 0..3
    const int cseg = lane & 7;           // 0..7
    const float* csrc = myrel + (size_t)crow * RS + cseg * 4;
    const u32 cdst = raw_su + (u32)(crow * RSTR * 4 + cseg * 16);

#define ISSUE_CHUNK(cc, buf)                                              \
    do {                                                                  \
        const u32 d_ = cdst + (u32)((buf) * RBUFF * 4);                   \
        const float* s_ = csrc + 32 * (cc);                               \
        cpasync16(d_,                         s_);                        \
        cpasync16(d_ + 4u  * RSTR * 4u, s_ + (size_t)4  * RS);            \
        cpasync16(d_ + 8u  * RSTR * 4u, s_ + (size_t)8  * RS);            \
        cpasync16(d_ + 12u * RSTR * 4u, s_ + (size_t)12 * RS);            \
    } while (0)

    // ---- prefetch chunks 0,1 ----
    ISSUE_CHUNK(0, 0); cp_commit();
    ISSUE_CHUNK(1, 1); cp_commit();

    // ---- stage v_s, bias ----
    for (int i = tid; i < D_; i += TPB) {
        int h = i >> 6, e = i & 63;
        v_s[i] = v[(((size_t)b * H_ + h) * S_ + sk) * E_ + e];
    }
    if (tid < L_) bias_s[tid] = bias[tid];

    // ---- stage packed W (96KB from L2) ----
    {
        const uint4* src = (const uint4*)g_wp;
        uint4* dst = (uint4*)smem;
        for (int i = tid; i < WQ_U32 / 4; i += TPB) dst[i] = src[i];
    }
    __syncthreads();

    // ---- cv[l][h] = sum_e W[l, 64h+e] * v[h,e] ----
    for (int task = tid; task < L_ * H_; task += TPB) {
        int l = task / H_, h = task - l * H_;
        const float4* wr = (const float4*)(W + l * D_ + h * 64);
        const float4* vr = (const float4*)(v_s + h * 64);
        float s = 0.f;
#pragma unroll
        for (int e = 0; e < 16; ++e) {
            float4 a = wr[e], c = vr[e];
            s += a.x * c.x + a.y * c.y + a.z * c.z + a.w * c.w;
        }
        cv_s[task] = s;
    }
    __syncthreads();

    // ---- accumulators ----
    float acc[4][4];
#pragma unroll
    for (int nt = 0; nt < 4; ++nt)
#pragma unroll
        for (int q = 0; q < 4; ++q) acc[nt][q] = 0.f;

    // pv pipeline (h = chunk>>1)
    const float* ptb = g_pt + (((size_t)b * H_) * S_ + sk) * S_ + 16 * w;
    float pvA = __ldg(ptb + g);
    float pvB = __ldg(ptb + g + 8);
    float pvAn = pvA, pvBn = pvB;

    // mainloop: 4 outer x 6 static chunks (lcm of NBUF=3 and h-period=2)
#pragma unroll 1
    for (int c0 = 0; c0 < CH; c0 += 6) {
#pragma unroll
        for (int u = 0; u < 6; ++u) {
            const int cc = c0 + u;

            // h-boundary: cc even (and not first) -> adopt prefetched pv
            if ((u & 1) == 0 && cc > 0) { pvA = pvAn; pvB = pvBn; }

            // issue chunk cc+2 into buf (u+2)%3; commit unconditionally
            if (cc + 2 < CH) ISSUE_CHUNK(cc + 2, (u + 2) % 3);
            cp_commit();
            cp_wait2();          // chunk cc resident

            // prefetch pv for next h at odd cc
            if ((u & 1) == 1) {
                int hn = (cc + 1) >> 1;
                if (hn > H_ - 1) hn = H_ - 1;
                pvAn = __ldg(ptb + (size_t)hn * (S_ * S_) + g);
                pvBn = __ldg(ptb + (size_t)hn * (S_ * S_) + g + 8);
            }

            // load this chunk's 16 floats (2 rows x 2 k-halves) via LDS.128
            const float* rp = rawb + (u % 3) * RBUFF;
            const float4 rl0 = *(const float4*)(rp + g * RSTR + tg * 4);
            const float4 rl1 = *(const float4*)(rp + g * RSTR + 16 + tg * 4);
            const float4 rh0 = *(const float4*)(rp + (g + 8) * RSTR + tg * 4);
            const float4 rh1 = *(const float4*)(rp + (g + 8) * RSTR + 16 + tg * 4);

            // 4 ksteps: s = 2h+e; e=0 -> (x,y), e=1 -> (z,w)
#pragma unroll
            for (int s = 0; s < 4; ++s) {
                const float4& lo = (s < 2) ? rl0 : rl1;
                const float4& hi = (s < 2) ? rh0 : rh1;
                float lx = (s & 1) ? lo.z : lo.x;
                float ly = (s & 1) ? lo.w : lo.y;
                float hx = (s & 1) ? hi.z : hi.x;
                float hy = (s & 1) ? hi.w : hi.y;
                u32 a[4];
                a[0] = f2tf32(lx * pvA);
                a[1] = f2tf32(hx * pvB);
                a[2] = f2tf32(ly * pvA);
                a[3] = f2tf32(hy * pvB);

                const u32* wp = wsg + ((4 * cc + s) * 4 + tg) * 8;
                const uint4 q0 = *(const uint4*)(wp);
                const uint4 q1 = *(const uint4*)(wp + 4);
                mma_tf32(acc[0], a, q0.x, q0.y);
                mma_tf32(acc[1], a, q0.z, q0.w);
                mma_tf32(acc[2], a, q1.x, q1.y);
                mma_tf32(acc[3], a, q1.z, q1.w);
            }
        }
    }
#undef ISSUE_CHUNK

    // ---- epilogue: bias + v-correction + store ----
    const float* pte = g_pt + (((size_t)b * H_) * S_ + sk) * S_;
    float* ob = out + ((size_t)(b * S_ + sk) * L_) * S_;
#pragma unroll
    for (int i = 0; i < 2; ++i) {
        const int row = 16 * w + g + 8 * i;
        float pr[H_];
#pragma unroll
        for (int h = 0; h < H_; ++h)
            pr[h] = __ldg(pte + (size_t)h * (S_ * S_) + row);
#pragma unroll
        for (int nt = 0; nt < 4; ++nt) {
#pragma unroll
            for (int j = 0; j < 2; ++j) {
                const int l = 8 * nt + 2 * tg + j;
                if (l < L_) {
                    float val = acc[nt][2 * i + j] + bias_s[l];
#pragma unroll
                    for (int h = 0; h < H_; ++h)
                        val += pr[h] * cv_s[l * H_ + h];
                    ob[(size_t)l * S_ + row] = val;
                }
            }
        }
    }
}

extern "C" void kernel_launch(void* const* d_in, const int* in_sizes, int n_in,
                              void* d_out, int out_size) {
    const float* p    = (const float*)d_in[0];
    const float* v    = (const float*)d_in[1];
    const float* rel  = (const float*)d_in[2];
    const float* W    = (const float*)d_in[3];
    const float* bias = (const float*)d_in[4];
    float* out = (float*)d_out;

    dim3 gt(S_ / 32, S_ / 32, B_ * H_ + 1);
    prep_kernel<<<gt, dim3(32, 8)>>>(p, W);

    const int smem_bytes = SMEM_FLOATS * (int)sizeof(float);  // 225712
    cudaFuncSetAttribute(mhs_mma_kernel,
                         cudaFuncAttributeMaxDynamicSharedMemorySize, smem_bytes);
    mhs_mma_kernel<<<B_ * S_, TPB, smem_bytes>>>(v, rel, W, bias, out);
}

// round 12
// speedup vs baseline: 1.2316x; 1.2316x over previous
#include <cuda_runtime.h>
#include <cuda_bf16.h>
#include <cstdint>

#define B_ 2
#define H_ 12
#define S_ 256
#define E_ 64
#define D_ 768
#define L_ 25
#define RS (S_ * D_)      // rel sq-stride (floats)
#define CH 24             // k32 chunks per tile
#define NTILE 512
#define GRID 148
#define RSTR 40           // raw row stride (floats) = 160B
#define RBUFF (16 * RSTR) // floats per raw buffer (640)
#define TPB 512
#define GSTRIDE 3076      // u32 per g-block of W frags (conflict-free)
#define WQ_U32 (8 * GSTRIDE)  // 24608

typedef unsigned long long u64;
typedef unsigned int u32;

// ---- smem layout (float-slot offsets) ----
#define OFF_WS   0                      // 24608 u32
#define OFF_RAW  24608                  // 16 warps x 3 bufs x 640 = 30720
#define SMEM_FLOATS 55328               // 221312 bytes

__device__ float g_pt[B_ * H_ * S_ * S_];
__device__ u32   g_wp[WQ_U32];
__device__ float g_cv[NTILE * 300];     // per-(b,sk): cv[l*12+h]

__device__ __forceinline__ u32 f2tf32(float x) {
    u32 r;
    asm("cvt.rna.tf32.f32 %0, %1;" : "=r"(r) : "f"(x));
    return r;
}

// z<24: transpose p; z==24: pack W into g-major tf32 frag layout (R11 layout).
__global__ void prep_kernel(const float* __restrict__ p, const float* __restrict__ W) {
    if (blockIdx.z == 24) {
        int flat = blockIdx.y * 8 + blockIdx.x;
        int t = flat * 256 + threadIdx.y * 32 + threadIdx.x;
        if (t >= 96 * 32 * 4) return;
        int ks = t >> 7;
        int r  = t & 127;
        int n  = r >> 2, tg = r & 3;
        int c = ks >> 2, s = ks & 3;
        int h = s >> 1, e = s & 1;
        int k0 = c * 32 + h * 16 + tg * 4 + e * 2;
#pragma unroll
        for (int j = 0; j < 2; ++j) {
            float wv = (n < L_) ? W[n * D_ + k0 + j] : 0.0f;
            g_wp[(n & 7) * GSTRIDE + (ks * 4 + tg) * 8 + (n >> 3) * 2 + j] = f2tf32(wv);
        }
        return;
    }
    __shared__ float tile[32][33];
    int bh = blockIdx.z, x0 = blockIdx.x * 32, y0 = blockIdx.y * 32;
    int tx = threadIdx.x, ty = threadIdx.y;
    const float* src = p + (size_t)bh * (S_ * S_);
#pragma unroll
    for (int j = 0; j < 32; j += 8)
        tile[ty + j][tx] = src[(size_t)(y0 + ty + j) * S_ + (x0 + tx)];
    __syncthreads();
    float* dst = g_pt + (size_t)bh * (S_ * S_);
#pragma unroll
    for (int j = 0; j < 32; j += 8)
        dst[(size_t)(x0 + ty + j) * S_ + (y0 + tx)] = tile[tx][ty + j];
}

// cv[t][l*12+h] = sum_e W[l,64h+e] * v[b,h,sk,e]   (t = b*256+sk)
__global__ void cv_kernel(const float* __restrict__ v, const float* __restrict__ W) {
    int t = blockIdx.x;
    int lh = threadIdx.x;
    if (lh >= 300) return;
    int l = lh / 12, h = lh - l * 12;
    int b = t >> 8, sk = t & 255;
    const float4* wr = (const float4*)(W + l * D_ + h * 64);
    const float4* vr = (const float4*)(v + (((size_t)b * H_ + h) * S_ + sk) * E_);
    float s = 0.f;
#pragma unroll
    for (int e = 0; e < 16; ++e) {
        float4 a = wr[e], c = vr[e];
        s += a.x * c.x + a.y * c.y + a.z * c.z + a.w * c.w;
    }
    g_cv[t * 300 + lh] = s;
}

__device__ __forceinline__ void cpasync16(u32 dst, const float* src) {
    asm volatile("cp.async.cg.shared.global [%0], [%1], 16;\n" :: "r"(dst), "l"(src));
}
__device__ __forceinline__ void cp_commit() {
    asm volatile("cp.async.commit_group;\n" ::: "memory");
}
__device__ __forceinline__ void cp_wait2() {
    asm volatile("cp.async.wait_group 2;\n" ::: "memory");
}
__device__ __forceinline__ u32 smem_u32(const void* p) {
    u32 r;
    asm("{ .reg .u64 t; cvta.to.shared.u64 t, %1; cvt.u32.u64 %0, t; }" : "=r"(r) : "l"(p));
    return r;
}
__device__ __forceinline__ void mma_tf32(float* c, const u32* a, u32 b0, u32 b1) {
    asm volatile(
        "mma.sync.aligned.m16n8k8.row.col.f32.tf32.tf32.f32 "
        "{%0,%1,%2,%3}, {%4,%5,%6,%7}, {%8,%9}, {%0,%1,%2,%3};"
        : "+f"(c[0]), "+f"(c[1]), "+f"(c[2]), "+f"(c[3])
        : "r"(a[0]), "r"(a[1]), "r"(a[2]), "r"(a[3]), "r"(b0), "r"(b1));
}

__global__ void __launch_bounds__(TPB, 1) mhs_mma_kernel(
    const float* __restrict__ rel,   // [B,S,S,768]
    const float* __restrict__ bias,  // [25]
    float* __restrict__ out)         // [B,S,25,S]
{
    extern __shared__ float smem[];
    const int tid  = threadIdx.x;
    const int w    = tid >> 5;
    const int lane = tid & 31;
    const int g    = lane >> 2;
    const int tg   = lane & 3;

    float* rawb   = smem + OFF_RAW + w * (3 * RBUFF);
    const u32 raw_su = smem_u32(rawb);
    const u32* wsg = (const u32*)smem + g * GSTRIDE;

    // cp.async lane mapping
    const int crow = lane >> 3;          // 0..3
    const int cseg = lane & 7;           // 0..7
    const u32 cdst = raw_su + (u32)(crow * RSTR * 4 + cseg * 16);

#define ISSUE_CHUNK(srcp, buf)                                            \
    do {                                                                  \
        const u32 d_ = cdst + (u32)((buf) * RBUFF * 4);                   \
        const float* s_ = (srcp);                                         \
        cpasync16(d_,                   s_);                              \
        cpasync16(d_ + 4u  * RSTR * 4u, s_ + (size_t)4  * RS);            \
        cpasync16(d_ + 8u  * RSTR * 4u, s_ + (size_t)8  * RS);            \
        cpasync16(d_ + 12u * RSTR * 4u, s_ + (size_t)12 * RS);            \
    } while (0)

    // per-lane rel offset within a tile slice
    const size_t lane_off = (size_t)(16 * w + crow) * RS + cseg * 4;

    // tile -> rel base
#define TILE_SRC(t) (rel + (size_t)((t) >> 8) * S_ * RS + (size_t)((t) & 255) * D_ + lane_off)

    // ---- initial prefetch: tile0 chunks 0,1 ----
    {
        const float* cs = TILE_SRC(blockIdx.x);
        ISSUE_CHUNK(cs, 0);      cp_commit();
        ISSUE_CHUNK(cs + 32, 1); cp_commit();
    }

    // ---- stage packed W once (96KB from L2) ----
    {
        const uint4* src = (const uint4*)g_wp;
        uint4* dst = (uint4*)smem;
        for (int i = tid; i < WQ_U32 / 4; i += TPB) dst[i] = src[i];
    }
    __syncthreads();   // the ONLY block barrier

    // ---- persistent tile loop, warps free-run ----
    for (int t = blockIdx.x; t < NTILE; t += GRID) {
        const int b  = t >> 8;
        const int sk = t & 255;
        const float* csrc = TILE_SRC(t);
        const int t2 = t + GRID;
        const bool has_next = (t2 < NTILE);
        const float* csrc2 = has_next ? TILE_SRC(t2) : csrc;

        const float* ptb = g_pt + ((size_t)b * H_) * (S_ * S_) + sk * S_ + 16 * w;
        float pvA = __ldg(ptb + g);
        float pvB = __ldg(ptb + g + 8);
        float pvAn = pvA, pvBn = pvB;

        float acc[4][4];
#pragma unroll
        for (int nt = 0; nt < 4; ++nt)
#pragma unroll
            for (int q = 0; q < 4; ++q) acc[nt][q] = 0.f;

#pragma unroll
        for (int u = 0; u < CH; ++u) {
            if ((u & 1) == 0 && u > 0) { pvA = pvAn; pvB = pvBn; }

            // issue chunk u+2 (crosses into next tile at u>=22)
            if (u < CH - 2) {
                ISSUE_CHUNK(csrc + 32 * (u + 2), (u + 2) % 3);
            } else if (has_next) {
                ISSUE_CHUNK(csrc2 + 32 * (u - 22), (u + 2) % 3);
            }
            cp_commit();
            cp_wait2();          // chunk u resident

            if ((u & 1) == 1) {
                int hn = (u + 1) >> 1;
                if (hn > H_ - 1) hn = H_ - 1;
                pvAn = __ldg(ptb + (size_t)hn * (S_ * S_) + g);
                pvBn = __ldg(ptb + (size_t)hn * (S_ * S_) + g + 8);
            }

            const float* rp = rawb + (u % 3) * RBUFF;
            const float4 rl0 = *(const float4*)(rp + g * RSTR + tg * 4);
            const float4 rl1 = *(const float4*)(rp + g * RSTR + 16 + tg * 4);
            const float4 rh0 = *(const float4*)(rp + (g + 8) * RSTR + tg * 4);
            const float4 rh1 = *(const float4*)(rp + (g + 8) * RSTR + 16 + tg * 4);

#pragma unroll
            for (int s = 0; s < 4; ++s) {
                const float4& lo = (s < 2) ? rl0 : rl1;
                const float4& hi = (s < 2) ? rh0 : rh1;
                float lx = (s & 1) ? lo.z : lo.x;
                float ly = (s & 1) ? lo.w : lo.y;
                float hx = (s & 1) ? hi.z : hi.x;
                float hy = (s & 1) ? hi.w : hi.y;
                u32 a[4];
                a[0] = f2tf32(lx * pvA);
                a[1] = f2tf32(hx * pvB);
                a[2] = f2tf32(ly * pvA);
                a[3] = f2tf32(hy * pvB);

                const u32* wp = wsg + ((4 * u + s) * 4 + tg) * 8;
                const uint4 q0 = *(const uint4*)(wp);
                const uint4 q1 = *(const uint4*)(wp + 4);
                mma_tf32(acc[0], a, q0.x, q0.y);
                mma_tf32(acc[1], a, q0.z, q0.w);
                mma_tf32(acc[2], a, q1.x, q1.y);
                mma_tf32(acc[3], a, q1.z, q1.w);
            }
        }

        // ---- per-warp epilogue (no barriers) ----
        const float* pte = g_pt + ((size_t)b * H_) * (S_ * S_) + sk * S_;
        const float* cvp = g_cv + (size_t)t * 300;
        float* ob = out + ((size_t)t * L_) * S_;
#pragma unroll
        for (int i = 0; i < 2; ++i) {
            const int row = 16 * w + g + 8 * i;
            float pr[H_];
#pragma unroll
            for (int h = 0; h < H_; ++h)
                pr[h] = __ldg(pte + (size_t)h * (S_ * S_) + row);
#pragma unroll
            for (int nt = 0; nt < 4; ++nt) {
#pragma unroll
                for (int j = 0; j < 2; ++j) {
                    const int l = 8 * nt + 2 * tg + j;
                    if (l < L_) {
                        float val = acc[nt][2 * i + j] + __ldg(bias + l);
#pragma unroll
                        for (int h = 0; h < H_; ++h)
                            val += pr[h] * __ldg(cvp + l * H_ + h);
                        ob[(size_t)l * S_ + row] = val;
                    }
                }
            }
        }
    }
#undef ISSUE_CHUNK
#undef TILE_SRC
}

extern "C" void kernel_launch(void* const* d_in, const int* in_sizes, int n_in,
                              void* d_out, int out_size) {
    const float* p    = (const float*)d_in[0];
    const float* v    = (const float*)d_in[1];
    const float* rel  = (const float*)d_in[2];
    const float* W    = (const float*)d_in[3];
    const float* bias = (const float*)d_in[4];
    float* out = (float*)d_out;

    dim3 gt(S_ / 32, S_ / 32, B_ * H_ + 1);
    prep_kernel<<<gt, dim3(32, 8)>>>(p, W);
    cv_kernel<<<NTILE, 320>>>(v, W);

    const int smem_bytes = SMEM_FLOATS * (int)sizeof(float);  // 221312
    cudaFuncSetAttribute(mhs_mma_kernel,
                         cudaFuncAttributeMaxDynamicSharedMemorySize, smem_bytes);
    mhs_mma_kernel<<<GRID, TPB, smem_bytes>>>(rel, bias, out);
}